// round 13
// baseline (speedup 1.0000x reference)
#include <cuda_runtime.h>
#include <cuda_fp16.h>
#include <cstdint>

// ---------------------------------------------------------------------------
// y[m, n*410+f] = u[m,f] + sx[m,n]*G[n,f] + c[f]
//   U[:, 0:410] = X @ Wfc^T,  U[:, 410:420] = X @ Wsel^T  (one fp16 GEMM)
//   G = Wfc @ Wexp, c = Wfc @ bexp + bfc
// GEMM: mma.sync m16n8k16 fp16, BM=128/BN=112/BK=64, cp.async 4-stage ring.
// NEW vs r12: 256 threads / 8 warps tiled 4(wm) x 2(wn) of 32x56 — 2 warps
// per SMSP to fill the 53% tensor-idle measured at 4 warps. Zero in-loop cvt.
// A pre-converted to fp16 (g_xh), B pre-converted in prep (g_Bt).
// ---------------------------------------------------------------------------

#define KDIM    4096
#define NFC     410
#define NCOLS   420
#define NBT     448
#define USTRIDE 432
#define MMAX    4096

#define BM 128
#define BN 112
#define BK 64                        // fp16 elems -> 128 bytes per smem row
#define NKT (KDIM / BK)              // 64
#define STAGES 4
#define TILE_A  (BM * BK * 2)        // 16384
#define TILE_B  (BN * BK * 2)        // 14336
#define STAGE_BYTES (TILE_A + TILE_B) // 30720

#define KSPLIT 8
#define PREPW  4576

__device__ float  g_U[MMAX * USTRIDE];
__device__ float  g_G[10 * 416];
__device__ float  g_c[416];
__device__ float  g_part[KSPLIT][PREPW];
__device__ __half g_Bt[NBT * KDIM];    // fp16 B (Wfc | Wsel | 0-pad)
__device__ __half g_xh[MMAX * KDIM];   // fp16 X

// ---------------- helpers ----------------------------------------------------
__device__ __forceinline__ uint32_t smem_u32(const void* p) {
    uint32_t a;
    asm("{ .reg .u64 t; cvta.to.shared.u64 t, %1; cvt.u32.u64 %0, t; }" : "=r"(a) : "l"(p));
    return a;
}
__device__ __forceinline__ void cp16(uint32_t dst, const void* src) {
    asm volatile("cp.async.cg.shared.global [%0], [%1], 16;"
                 :: "r"(dst), "l"(src) : "memory");
}
__device__ __forceinline__ void cp_commit() {
    asm volatile("cp.async.commit_group;" ::: "memory");
}
__device__ __forceinline__ void cp_wait2() {
    asm volatile("cp.async.wait_group 2;" ::: "memory");
}
__device__ __forceinline__ void ldsm4(uint32_t* r, uint32_t a) {
    asm volatile("ldmatrix.sync.aligned.m8n8.x4.shared.b16 {%0,%1,%2,%3}, [%4];"
                 : "=r"(r[0]), "=r"(r[1]), "=r"(r[2]), "=r"(r[3]) : "r"(a));
}
__device__ __forceinline__ void ldsm2(uint32_t* r, uint32_t a) {
    asm volatile("ldmatrix.sync.aligned.m8n8.x2.shared.b16 {%0,%1}, [%2];"
                 : "=r"(r[0]), "=r"(r[1]) : "r"(a));
}
__device__ __forceinline__ void mma16(float* c, const uint32_t* a, const uint32_t* b) {
    asm volatile(
        "mma.sync.aligned.m16n8k16.row.col.f32.f16.f16.f32 "
        "{%0,%1,%2,%3}, {%4,%5,%6,%7}, {%8,%9}, {%0,%1,%2,%3};"
        : "+f"(c[0]), "+f"(c[1]), "+f"(c[2]), "+f"(c[3])
        : "r"(a[0]), "r"(a[1]), "r"(a[2]), "r"(a[3]), "r"(b[0]), "r"(b[1]));
}

// ---------------------------------------------------------------------------
// x -> fp16 (8 elems/thread, vectorized)
// ---------------------------------------------------------------------------
__global__ void xh_kernel(const float* __restrict__ x) {
    int i = (blockIdx.x * 256 + threadIdx.x) * 8;
    float4 v0 = *reinterpret_cast<const float4*>(x + i);
    float4 v1 = *reinterpret_cast<const float4*>(x + i + 4);
    __half2 h0 = __floats2half2_rn(v0.x, v0.y);
    __half2 h1 = __floats2half2_rn(v0.z, v0.w);
    __half2 h2 = __floats2half2_rn(v1.x, v1.y);
    __half2 h3 = __floats2half2_rn(v1.z, v1.w);
    uint4 pk;
    pk.x = *reinterpret_cast<uint32_t*>(&h0);
    pk.y = *reinterpret_cast<uint32_t*>(&h1);
    pk.z = *reinterpret_cast<uint32_t*>(&h2);
    pk.w = *reinterpret_cast<uint32_t*>(&h3);
    *reinterpret_cast<uint4*>(g_xh + i) = pk;
}

// ---------------------------------------------------------------------------
// prep pass 1: G/c partials (f<410) + fp16 B materialization (all f<448)
// ---------------------------------------------------------------------------
__global__ void prep_part(const float* __restrict__ Wfc, const float* __restrict__ Wsel,
                          const float* __restrict__ Wexp, const float* __restrict__ bexp) {
    int f  = blockIdx.x;                 // 0..447
    int kz = blockIdx.y;
    int k0 = kz * 512;
    const float* src = nullptr;
    if (f < NFC)        src = Wfc + (size_t)f * KDIM + k0;
    else if (f < NCOLS) src = Wsel + (size_t)(f - NFC) * KDIM + k0;

    float acc[11];
#pragma unroll
    for (int v = 0; v < 11; v++) acc[v] = 0.f;

#pragma unroll
    for (int it = 0; it < 4; it++) {
        int k = it * 128 + threadIdx.x;
        float w = src ? src[k] : 0.f;
        g_Bt[(size_t)f * KDIM + k0 + k] = __float2half_rn(w);
        if (f < NFC) {
            const float* we = Wexp + (size_t)(k0 + k) * 10;
#pragma unroll
            for (int n = 0; n < 10; n++) acc[n] += w * we[n];
            acc[10] += w * bexp[k0 + k];
        }
    }
    if (f >= NFC) return;

    __shared__ float red[4][11];
    int lane = threadIdx.x & 31, warp = threadIdx.x >> 5;
#pragma unroll
    for (int v = 0; v < 11; v++) {
        float s = acc[v];
#pragma unroll
        for (int o = 16; o; o >>= 1) s += __shfl_xor_sync(0xffffffffu, s, o);
        if (lane == 0) red[warp][v] = s;
    }
    __syncthreads();
    if (threadIdx.x < 11) {
        float s = red[0][threadIdx.x] + red[1][threadIdx.x] +
                  red[2][threadIdx.x] + red[3][threadIdx.x];
        g_part[kz][threadIdx.x * 416 + f] = s;
    }
}

__global__ void prep_combine(const float* __restrict__ bfc) {
    int i = blockIdx.x * 256 + threadIdx.x;
    if (i >= PREPW) return;
    float s = 0.f;
#pragma unroll
    for (int kz = 0; kz < KSPLIT; kz++) s += g_part[kz][i];
    if (i < 10 * 416) {
        g_G[i] = s;
    } else {
        int f = i - 10 * 416;
        g_c[f] = (f < NFC) ? s + bfc[f] : s;
    }
}

// ---------------------------------------------------------------------------
// GEMM: 128x112 block, 256 thr, 8 warps (4wm x 2wn) of 32x56, fp16 m16n8k16
// ---------------------------------------------------------------------------
__global__ __launch_bounds__(256, 1)
void gemm_kernel() {
    extern __shared__ char dyn[];
    char* bufs = (char*)(((uintptr_t)dyn + 1023) & ~(uintptr_t)1023);
    const uint32_t bufs_u32 = smem_u32(bufs);

    const int tid  = threadIdx.x;
    const int lane = tid & 31;
    const int warp = tid >> 5;
    const int wm   = warp >> 1;        // 0..3
    const int wn   = warp & 1;         // 0..1
    const int m0   = blockIdx.y * BM;
    const int n0   = blockIdx.x * BN;

    // ---- A loader: row tid>>1 (0..127), 4 consecutive 16B chunks ----
    const int arow = tid >> 1;
    const int ac0  = (tid & 1) * 4;
    uint32_t adst[4];
#pragma unroll
    for (int i = 0; i < 4; i++)
        adst[i] = (uint32_t)(arow * 128 + (((ac0 + i) * 16) ^ ((arow & 7) << 4)));
    const char* aglob = (const char*)(g_xh + (size_t)(m0 + arow) * KDIM) + ac0 * 16;

    // ---- B loader: threads 0..223, row tid>>1 (0..111), 4 chunks ----
    const bool bvalid = (tid < 224);
    const char* bglob = (const char*)g_Bt;
    if (bvalid) bglob = (const char*)(g_Bt + (size_t)(n0 + arow) * KDIM) + ac0 * 16;

    auto issue = [&](int kt) {
        int stage = kt & (STAGES - 1);
        uint32_t sb = bufs_u32 + stage * STAGE_BYTES;
        const char* as = aglob + (size_t)kt * 128;
#pragma unroll
        for (int i = 0; i < 4; i++) cp16(sb + adst[i], as + i * 16);
        if (bvalid) {
            const char* bs = bglob + (size_t)kt * 128;
#pragma unroll
            for (int i = 0; i < 4; i++) cp16(sb + TILE_A + adst[i], bs + i * 16);
        }
    };

    // ---- fragment constants (validated r11/r12 byte addressing) ----
    const uint32_t aoff  = (uint32_t)((wm * 32 + (lane & 15)) * 128);
    const uint32_t xS    = (uint32_t)((lane & 7) << 4);
    const uint32_t hA    = (lane & 16) ? 16u : 0u;
    const uint32_t boffp = (uint32_t)((wn * 56 + (lane & 7) + ((lane & 16) ? 8 : 0)) * 128);
    const uint32_t boff2 = (uint32_t)((wn * 56 + 48 + (lane & 7)) * 128);
    const uint32_t hB    = (lane & 8) ? 16u : 0u;

    float acc[2][7][4];
#pragma unroll
    for (int mi = 0; mi < 2; mi++)
#pragma unroll
        for (int nj = 0; nj < 7; nj++)
#pragma unroll
            for (int q = 0; q < 4; q++) acc[mi][nj][q] = 0.f;

    issue(0); cp_commit();
    issue(1); cp_commit();
    issue(2); cp_commit();

    uint32_t a[2][2][4], bp[2][3][4], b6[2][2];

#pragma unroll 1
    for (int kt = 0; kt < NKT; kt++) {
        cp_wait2();
        __syncthreads();
        if (kt + 3 < NKT) issue(kt + 3);
        cp_commit();

        const uint32_t As = bufs_u32 + (kt & (STAGES - 1)) * STAGE_BYTES;
        const uint32_t Bs = As + TILE_A;

        // preload ks=0
        {
            const uint32_t ka = hA ^ xS;
            const uint32_t kb = hB ^ xS;
#pragma unroll
            for (int mi = 0; mi < 2; mi++) ldsm4(a[0][mi], As + aoff + mi * 2048 + ka);
#pragma unroll
            for (int p = 0; p < 3; p++)   ldsm4(bp[0][p], Bs + boffp + p * 2048 + kb);
            ldsm2(b6[0], Bs + boff2 + kb);
        }

#pragma unroll
        for (int ks = 0; ks < 4; ks++) {
            const int cur = ks & 1;
            const int nxt = cur ^ 1;
            if (ks < 3) {
                const uint32_t ka = (uint32_t)((ks + 1) * 32 + hA) ^ xS;
                const uint32_t kb = (uint32_t)((ks + 1) * 32 + hB) ^ xS;
#pragma unroll
                for (int mi = 0; mi < 2; mi++) ldsm4(a[nxt][mi], As + aoff + mi * 2048 + ka);
#pragma unroll
                for (int p = 0; p < 3; p++)   ldsm4(bp[nxt][p], Bs + boffp + p * 2048 + kb);
                ldsm2(b6[nxt], Bs + boff2 + kb);
            }
#pragma unroll
            for (int mi = 0; mi < 2; mi++) {
#pragma unroll
                for (int p = 0; p < 3; p++) {
                    mma16(acc[mi][2 * p],     a[cur][mi], &bp[cur][p][0]);
                    mma16(acc[mi][2 * p + 1], a[cur][mi], &bp[cur][p][2]);
                }
                mma16(acc[mi][6], a[cur][mi], b6[cur]);
            }
        }
    }

    // ---- write U (guard pad columns) ----
    const int gid = lane >> 2;
    const int tig = lane & 3;
#pragma unroll
    for (int mi = 0; mi < 2; mi++) {
        int r0 = m0 + wm * 32 + mi * 16 + gid;
#pragma unroll
        for (int nj = 0; nj < 7; nj++) {
            int col = n0 + wn * 56 + nj * 8 + 2 * tig;
            if (col < NCOLS) {
                *reinterpret_cast<float2*>(&g_U[(size_t)r0 * USTRIDE + col]) =
                    make_float2(acc[mi][nj][0], acc[mi][nj][1]);
                *reinterpret_cast<float2*>(&g_U[(size_t)(r0 + 8) * USTRIDE + col]) =
                    make_float2(acc[mi][nj][2], acc[mi][nj][3]);
            }
        }
    }
}

// ---------------------------------------------------------------------------
// epilogue (fastest measured): float2, 1 row/block
// ---------------------------------------------------------------------------
__global__ void epi_kernel(const float* __restrict__ bsel, float* __restrict__ out) {
    int m = blockIdx.x;
    __shared__ float sx[10];
    if (threadIdx.x < 10)
        sx[threadIdx.x] = g_U[(size_t)m * USTRIDE + NFC + threadIdx.x] + bsel[threadIdx.x];
    __syncthreads();
    const float* Ur = g_U + (size_t)m * USTRIDE;
    float* orow = out + (size_t)m * 4096;
#pragma unroll 1
    for (int n = 0; n < 10; n++) {
        int base = n * NFC;
        float sxn = sx[n];
        int lim = (n == 9) ? (4096 - base) : NFC;
        const float* Gn = g_G + n * 416;
        for (int f = threadIdx.x * 2; f < lim; f += 512) {
            float2 u = *reinterpret_cast<const float2*>(Ur + f);
            float2 g = *reinterpret_cast<const float2*>(Gn + f);
            float2 cc = *reinterpret_cast<const float2*>(g_c + f);
            float2 r;
            r.x = fmaf(sxn, g.x, u.x + cc.x);
            r.y = fmaf(sxn, g.y, u.y + cc.y);
            *reinterpret_cast<float2*>(orow + base + f) = r;
        }
    }
}

// ---------------------------------------------------------------------------
extern "C" void kernel_launch(void* const* d_in, const int* in_sizes, int n_in,
                              void* d_out, int out_size) {
    const float* x    = (const float*)d_in[0];
    const float* Wsel = (const float*)d_in[1];
    const float* bsel = (const float*)d_in[2];
    const float* Wexp = (const float*)d_in[3];
    const float* bexp = (const float*)d_in[4];
    const float* Wfc  = (const float*)d_in[5];
    const float* bfc  = (const float*)d_in[6];
    float* out = (float*)d_out;

    int M = in_sizes[0] / KDIM;   // 4096

    const int smem_bytes = STAGES * STAGE_BYTES + 1024;   // 123904
    cudaFuncSetAttribute(gemm_kernel, cudaFuncAttributeMaxDynamicSharedMemorySize, smem_bytes);

    xh_kernel<<<(M * KDIM) / (256 * 8), 256>>>(x);
    prep_part<<<dim3(NBT, KSPLIT), 128>>>(Wfc, Wsel, Wexp, bexp);
    prep_combine<<<(PREPW + 255) / 256, 256>>>(bfc);
    dim3 grid(4, M / BM);   // 4 x 32 = 128 blocks
    gemm_kernel<<<grid, 256, smem_bytes>>>();
    epi_kernel<<<M, 256>>>(bsel, out);
}